// round 8
// baseline (speedup 1.0000x reference)
#include <cuda_runtime.h>
#include <math.h>

#define HID 128
#define MAXN 50000
#define MAXE 800000
#define SM1_BLOCKS 512
#define AS_LD 129
#define SMEM_GEMM ((128 * AS_LD + 128 * 128) * 4)

__device__ float g_u[MAXN * HID];   // h @ Wa
__device__ float g_v[MAXN * HID];   // h @ Wb
__device__ float g_a[MAXE];         // per-edge logits
__device__ float g_pm[SM1_BLOCKS];  // per-block max
__device__ float g_ps[SM1_BLOCKS];  // per-block sumexp
__device__ float g_M, g_S;

// ---------------------------------------------------------------------------
// Tiled GEMM machinery: C_tile[128x128] = A_tile[128x128] @ B[128x128]
// ---------------------------------------------------------------------------
__device__ __forceinline__ void load_tiles(const float* __restrict__ A,
                                           const float* __restrict__ B,
                                           int m_base, int n_rows,
                                           float* As, float* Bs, int tid) {
    #pragma unroll
    for (int i = tid; i < 4096; i += 256)
        reinterpret_cast<float4*>(Bs)[i] = reinterpret_cast<const float4*>(B)[i];
    int warp = tid >> 5, lane = tid & 31;
    for (int r = warp; r < 128; r += 8) {
        int m = m_base + r;
        float4 va = make_float4(0.f, 0.f, 0.f, 0.f);
        if (m < n_rows)
            va = reinterpret_cast<const float4*>(A + (size_t)m * HID)[lane];
        float* dst = As + r * AS_LD + lane * 4;
        dst[0] = va.x; dst[1] = va.y; dst[2] = va.z; dst[3] = va.w;
    }
}

__device__ __forceinline__ void gemm_tile(const float* As, const float* Bs,
                                          int tx, int ty, float acc[8][8]) {
    const float* Ap = As + (ty * 8) * AS_LD;
    #pragma unroll 4
    for (int k = 0; k < 128; ++k) {
        float a[8];
        #pragma unroll
        for (int i = 0; i < 8; ++i) a[i] = Ap[i * AS_LD + k];
        float4 b0 = *reinterpret_cast<const float4*>(Bs + k * 128 + tx * 8);
        float4 b1 = *reinterpret_cast<const float4*>(Bs + k * 128 + tx * 8 + 4);
        float b[8] = {b0.x, b0.y, b0.z, b0.w, b1.x, b1.y, b1.z, b1.w};
        #pragma unroll
        for (int i = 0; i < 8; ++i)
            #pragma unroll
            for (int j = 0; j < 8; ++j)
                acc[i][j] = fmaf(a[i], b[j], acc[i][j]);
    }
}

// ---------------------------------------------------------------------------
// K1: u = h @ Wa / v = h @ Wb
// ---------------------------------------------------------------------------
__global__ void __launch_bounds__(256, 1)
k_gemm_uv(const float* __restrict__ A, const float* __restrict__ B,
          int n_rows, int which) {
    extern __shared__ float smem[];
    float* As = smem;
    float* Bs = smem + 128 * AS_LD;
    int tid = threadIdx.x;
    int m_base = blockIdx.x * 128;

    load_tiles(A, B, m_base, n_rows, As, Bs, tid);
    __syncthreads();

    int tx = tid & 15, ty = tid >> 4;
    float acc[8][8];
    #pragma unroll
    for (int i = 0; i < 8; ++i)
        #pragma unroll
        for (int j = 0; j < 8; ++j) acc[i][j] = 0.f;

    gemm_tile(As, Bs, tx, ty, acc);

    float* C = which ? g_v : g_u;
    #pragma unroll
    for (int i = 0; i < 8; ++i) {
        int m = m_base + ty * 8 + i;
        if (m < n_rows) {
            float4 c0 = make_float4(acc[i][0], acc[i][1], acc[i][2], acc[i][3]);
            float4 c1 = make_float4(acc[i][4], acc[i][5], acc[i][6], acc[i][7]);
            float* cp = C + (size_t)m * HID + tx * 8;
            *reinterpret_cast<float4*>(cp) = c0;
            *reinterpret_cast<float4*>(cp + 4) = c1;
        }
    }
}

// ---------------------------------------------------------------------------
// K2: fused edge GEMM + logit epilogue
// ---------------------------------------------------------------------------
__global__ void __launch_bounds__(256, 1)
k_edge(const float* __restrict__ ea, const float* __restrict__ Wc,
       const int* __restrict__ ei,
       const float* __restrict__ b1, const float* __restrict__ W2,
       const float* __restrict__ b2, int n_edges) {
    extern __shared__ float smem[];
    float* As = smem;
    float* Bs = smem + 128 * AS_LD;
    __shared__ int sR[128], sC[128];

    int tid = threadIdx.x;
    int m_base = blockIdx.x * 128;

    if (tid < 128) {
        int e = m_base + tid;
        int r = 0, c = 0;
        if (e < n_edges) { r = ei[e]; c = ei[n_edges + e]; }
        sR[tid] = r; sC[tid] = c;
    }
    load_tiles(ea, Wc, m_base, n_edges, As, Bs, tid);
    __syncthreads();

    int tx = tid & 15, ty = tid >> 4;
    float acc[8][8];
    #pragma unroll
    for (int i = 0; i < 8; ++i)
        #pragma unroll
        for (int j = 0; j < 8; ++j) acc[i][j] = 0.f;

    gemm_tile(As, Bs, tx, ty, acc);

    float b1r[8], w2r[8];
    #pragma unroll
    for (int j = 0; j < 8; ++j) {
        b1r[j] = b1[tx * 8 + j];
        w2r[j] = W2[tx * 8 + j];
    }
    float bias2 = b2[0];

    #pragma unroll
    for (int i = 0; i < 8; ++i) {
        int eidx = m_base + ty * 8 + i;
        bool valid = (eidx < n_edges);
        int r = sR[ty * 8 + i], c = sC[ty * 8 + i];
        const float4* up = reinterpret_cast<const float4*>(g_u + (size_t)r * HID + tx * 8);
        const float4* vp = reinterpret_cast<const float4*>(g_v + (size_t)c * HID + tx * 8);
        float4 u0 = up[0], u1 = up[1];
        float4 v0 = vp[0], v1 = vp[1];
        float uv[8] = {u0.x + v0.x, u0.y + v0.y, u0.z + v0.z, u0.w + v0.w,
                       u1.x + v1.x, u1.y + v1.y, u1.z + v1.z, u1.w + v1.w};
        float s = 0.f;
        #pragma unroll
        for (int j = 0; j < 8; ++j) {
            float pre = acc[i][j] + uv[j] + b1r[j];
            float el = pre > 0.f ? pre : expm1f(pre);
            s = fmaf(el, w2r[j], s);
        }
        #pragma unroll
        for (int off = 8; off > 0; off >>= 1)
            s += __shfl_down_sync(0xffffffffu, s, off, 16);
        if (tx == 0 && valid) {
            float av = s + bias2;
            av = av >= 0.f ? av : 0.2f * av;
            g_a[eidx] = av;
        }
    }
}

// ---------------------------------------------------------------------------
// K3/K4: global softmax reduction  (FIXED: store block sum sh[0], not local s)
// ---------------------------------------------------------------------------
__global__ void k_sm1(int n) {
    __shared__ float sh[256];
    int tid = threadIdx.x;
    float m = -1e30f;
    for (int i = blockIdx.x * 256 + tid; i < n; i += gridDim.x * 256)
        m = fmaxf(m, g_a[i]);
    sh[tid] = m; __syncthreads();
    for (int off = 128; off > 0; off >>= 1) {
        if (tid < off) sh[tid] = fmaxf(sh[tid], sh[tid + off]);
        __syncthreads();
    }
    float bm = sh[0]; __syncthreads();
    float s = 0.f;
    for (int i = blockIdx.x * 256 + tid; i < n; i += gridDim.x * 256)
        s += expf(g_a[i] - bm);
    sh[tid] = s; __syncthreads();
    for (int off = 128; off > 0; off >>= 1) {
        if (tid < off) sh[tid] += sh[tid + off];
        __syncthreads();
    }
    if (tid == 0) { g_pm[blockIdx.x] = bm; g_ps[blockIdx.x] = sh[0]; }  // <-- THE FIX
}

__global__ void k_sm2() {
    __shared__ float sh[SM1_BLOCKS];
    int tid = threadIdx.x;
    sh[tid] = g_pm[tid]; __syncthreads();
    for (int off = SM1_BLOCKS / 2; off > 0; off >>= 1) {
        if (tid < off) sh[tid] = fmaxf(sh[tid], sh[tid + off]);
        __syncthreads();
    }
    float M = sh[0]; __syncthreads();
    sh[tid] = g_ps[tid] * expf(g_pm[tid] - M); __syncthreads();
    for (int off = SM1_BLOCKS / 2; off > 0; off >>= 1) {
        if (tid < off) sh[tid] += sh[tid + off];
        __syncthreads();
    }
    if (tid == 0) { g_M = M; g_S = sh[0]; }
}

// ---------------------------------------------------------------------------
// K5/K6: zero + scatter
// ---------------------------------------------------------------------------
__global__ void k_zero(float* __restrict__ out, int n) {
    for (int i = blockIdx.x * blockDim.x + threadIdx.x; i < n;
         i += gridDim.x * blockDim.x)
        out[i] = 0.f;
}

__global__ void k_scatter(const int* __restrict__ ei,
                          const float* __restrict__ h,
                          float* __restrict__ out, int n_edges) {
    int gw = (blockIdx.x * blockDim.x + threadIdx.x) >> 5;
    int lane = threadIdx.x & 31;
    int nw = (gridDim.x * blockDim.x) >> 5;
    float M = g_M;
    float invS = 1.0f / g_S;
    for (int e = gw; e < n_edges; e += nw) {
        int r = ei[e];
        int c = ei[n_edges + e];
        float alpha = expf(g_a[e] - M) * invS;
        float4 hv = reinterpret_cast<const float4*>(h + (size_t)c * HID)[lane];
        float* op = out + (size_t)r * HID + lane * 4;
        atomicAdd(op + 0, alpha * hv.x);
        atomicAdd(op + 1, alpha * hv.y);
        atomicAdd(op + 2, alpha * hv.z);
        atomicAdd(op + 3, alpha * hv.w);
    }
}

// ---------------------------------------------------------------------------
extern "C" void kernel_launch(void* const* d_in, const int* in_sizes, int n_in,
                              void* d_out, int out_size) {
    const float* h  = (const float*)d_in[0];
    const int*   ei = (const int*)d_in[1];   // int32 (verified by telemetry)
    const float* ea = (const float*)d_in[2];
    const float* W1 = (const float*)d_in[3];
    const float* b1 = (const float*)d_in[4];
    const float* W2 = (const float*)d_in[5];
    const float* b2 = (const float*)d_in[6];
    float* out = (float*)d_out;

    int n_nodes = in_sizes[0] / HID;
    int n_edges = in_sizes[2] / HID;

    cudaFuncSetAttribute(k_gemm_uv, cudaFuncAttributeMaxDynamicSharedMemorySize, SMEM_GEMM);
    cudaFuncSetAttribute(k_edge,    cudaFuncAttributeMaxDynamicSharedMemorySize, SMEM_GEMM);

    int node_blocks = (n_nodes + 127) / 128;
    int edge_blocks = (n_edges + 127) / 128;

    k_zero<<<2048, 256>>>(out, n_nodes * HID);
    k_gemm_uv<<<node_blocks, 256, SMEM_GEMM>>>(h, W1,             n_nodes, 0);
    k_gemm_uv<<<node_blocks, 256, SMEM_GEMM>>>(h, W1 + HID * HID, n_nodes, 1);
    k_edge<<<edge_blocks, 256, SMEM_GEMM>>>(ea, W1 + 2 * HID * HID, ei, b1, W2, b2, n_edges);
    k_sm1<<<SM1_BLOCKS, 256>>>(n_edges);
    k_sm2<<<1, SM1_BLOCKS>>>();
    k_scatter<<<4096, 256>>>(ei, h, out, n_edges);
}

// round 12
// speedup vs baseline: 1.1938x; 1.1938x over previous
#include <cuda_runtime.h>
#include <mma.h>
#include <math.h>

using namespace nvcuda;

#define HID 128
#define MAXN_PAD 50048
#define MAXE 800000
#define SM1_BLOCKS 512
#define LDA 132

// smem layout (floats): [0:128) b1s, [128:256) w2s, [256:+16896) As, then Bs
#define SMF_B1 0
#define SMF_W2 128
#define SMF_A  256
#define SMF_B  (256 + 128 * LDA)
#define SMEM_TOTAL ((256 + 2 * 128 * LDA) * 4)

__device__ float g_u[MAXN_PAD * HID];
__device__ float g_v[MAXN_PAD * HID];
__device__ float g_a[MAXE];
__device__ float g_pm[SM1_BLOCKS];
__device__ float g_ps[SM1_BLOCKS];
__device__ float g_M, g_S;

// ---------------------------------------------------------------------------
// Shared tile loaders (row-major, LDA=132 padding, zero-fill OOB rows)
// ---------------------------------------------------------------------------
__device__ __forceinline__ void load_A(const float* __restrict__ src, int m_base,
                                       int n_rows, float* As, int tid) {
    #pragma unroll
    for (int i = tid; i < 128 * 32; i += 256) {
        int r = i >> 5, q = i & 31;
        float4 v = make_float4(0.f, 0.f, 0.f, 0.f);
        int m = m_base + r;
        if (m < n_rows)
            v = reinterpret_cast<const float4*>(src + (size_t)m * HID)[q];
        *reinterpret_cast<float4*>(As + r * LDA + q * 4) = v;
    }
}

__device__ __forceinline__ void load_B(const float* __restrict__ W, float* Bs, int tid) {
    #pragma unroll
    for (int i = tid; i < 128 * 32; i += 256) {
        int k = i >> 5, q = i & 31;
        float4 v = reinterpret_cast<const float4*>(W + (size_t)k * HID)[q];
        *reinterpret_cast<float4*>(Bs + k * LDA + q * 4) = v;
    }
}

// ---------------------------------------------------------------------------
// tf32 wmma mainloop: warp (wm, wn) computes 64x32 of C = A[128x128]@B[128x128]
// ---------------------------------------------------------------------------
using AccFrag = wmma::fragment<wmma::accumulator, 16, 16, 8, float>;

__device__ __forceinline__ void mma_loop(const float* As, const float* Bs,
                                         int wm, int wn, AccFrag acc[4][2]) {
    #pragma unroll
    for (int i = 0; i < 4; ++i)
        #pragma unroll
        for (int j = 0; j < 2; ++j)
            wmma::fill_fragment(acc[i][j], 0.f);

    #pragma unroll 4
    for (int kk = 0; kk < 128; kk += 8) {
        wmma::fragment<wmma::matrix_a, 16, 16, 8, wmma::precision::tf32,
                       wmma::row_major> af[4];
        wmma::fragment<wmma::matrix_b, 16, 16, 8, wmma::precision::tf32,
                       wmma::row_major> bf[2];
        #pragma unroll
        for (int i = 0; i < 4; ++i) {
            wmma::load_matrix_sync(af[i], As + (wm + i * 16) * LDA + kk, LDA);
            #pragma unroll
            for (int t = 0; t < af[i].num_elements; ++t)
                af[i].x[t] = wmma::__float_to_tf32(af[i].x[t]);
        }
        #pragma unroll
        for (int j = 0; j < 2; ++j) {
            wmma::load_matrix_sync(bf[j], Bs + kk * LDA + wn + j * 16, LDA);
            #pragma unroll
            for (int t = 0; t < bf[j].num_elements; ++t)
                bf[j].x[t] = wmma::__float_to_tf32(bf[j].x[t]);
        }
        #pragma unroll
        for (int i = 0; i < 4; ++i)
            #pragma unroll
            for (int j = 0; j < 2; ++j)
                wmma::mma_sync(acc[i][j], af[i], bf[j], acc[i][j]);
    }
}

// ---------------------------------------------------------------------------
// K1: C = A @ W (tf32), C padded so full-tile global stores are safe
// ---------------------------------------------------------------------------
__global__ void __launch_bounds__(256, 1)
k_tgemm(const float* __restrict__ A, const float* __restrict__ W,
        float* __restrict__ C, int n_rows) {
    extern __shared__ float smf[];
    float* As = smf + SMF_A;
    float* Bs = smf + SMF_B;
    int tid = threadIdx.x, wid = tid >> 5;
    int m_base = blockIdx.x * 128;
    int wm = (wid >> 2) * 64, wn = (wid & 3) * 32;

    load_A(A, m_base, n_rows, As, tid);
    load_B(W, Bs, tid);
    __syncthreads();

    AccFrag acc[4][2];
    mma_loop(As, Bs, wm, wn, acc);

    #pragma unroll
    for (int i = 0; i < 4; ++i)
        #pragma unroll
        for (int j = 0; j < 2; ++j)
            wmma::store_matrix_sync(
                C + (size_t)(m_base + wm + i * 16) * HID + wn + j * 16,
                acc[i][j], HID, wmma::mem_row_major);
}

// ---------------------------------------------------------------------------
// K2: edge GEMM (ea @ Wc) + fused logit epilogue
// ---------------------------------------------------------------------------
__global__ void __launch_bounds__(256, 1)
k_tedge(const float* __restrict__ ea, const float* __restrict__ Wc,
        const int* __restrict__ ei,
        const float* __restrict__ b1, const float* __restrict__ W2,
        const float* __restrict__ b2, int n_edges) {
    extern __shared__ float smf[];
    float* b1s = smf + SMF_B1;
    float* w2s = smf + SMF_W2;
    float* As  = smf + SMF_A;
    float* Bs  = smf + SMF_B;
    int tid = threadIdx.x, wid = tid >> 5;
    int m_base = blockIdx.x * 128;
    int wm = (wid >> 2) * 64, wn = (wid & 3) * 32;

    if (tid < 128) { b1s[tid] = b1[tid]; w2s[tid] = W2[tid]; }
    load_A(ea, m_base, n_edges, As, tid);
    load_B(Wc, Bs, tid);
    __syncthreads();

    AccFrag acc[4][2];
    mma_loop(As, Bs, wm, wn, acc);
    __syncthreads();               // all warps done reading As before reuse as Cs

    float* Cs = As;                // reuse A region for C (128 x LDA)
    #pragma unroll
    for (int i = 0; i < 4; ++i)
        #pragma unroll
        for (int j = 0; j < 2; ++j)
            wmma::store_matrix_sync(Cs + (wm + i * 16) * LDA + wn + j * 16,
                                    acc[i][j], LDA, wmma::mem_row_major);
    __syncthreads();

    if (tid < 128) {
        int e = m_base + tid;
        if (e < n_edges) {
            int r = ei[e];
            int c = ei[n_edges + e];
            const float4* up = reinterpret_cast<const float4*>(g_u + (size_t)r * HID);
            const float4* vp = reinterpret_cast<const float4*>(g_v + (size_t)c * HID);
            const float4* cp = reinterpret_cast<const float4*>(Cs + tid * LDA);
            const float4* b4 = reinterpret_cast<const float4*>(b1s);
            const float4* w4 = reinterpret_cast<const float4*>(w2s);
            float s = 0.f;
            #pragma unroll 8
            for (int q = 0; q < 32; ++q) {
                float4 cv = cp[q], uu = up[q], vv = vp[q], bb = b4[q], ww = w4[q];
                float p0 = cv.x + uu.x + vv.x + bb.x;
                float p1 = cv.y + uu.y + vv.y + bb.y;
                float p2 = cv.z + uu.z + vv.z + bb.z;
                float p3 = cv.w + uu.w + vv.w + bb.w;
                float e0 = p0 > 0.f ? p0 : expm1f(p0);
                float e1 = p1 > 0.f ? p1 : expm1f(p1);
                float e2 = p2 > 0.f ? p2 : expm1f(p2);
                float e3 = p3 > 0.f ? p3 : expm1f(p3);
                s = fmaf(e0, ww.x, s);
                s = fmaf(e1, ww.y, s);
                s = fmaf(e2, ww.z, s);
                s = fmaf(e3, ww.w, s);
            }
            float av = s + b2[0];
            av = av >= 0.f ? av : 0.2f * av;
            g_a[e] = av;
        }
    }
}

// ---------------------------------------------------------------------------
// K3/K4: global softmax reduction
// ---------------------------------------------------------------------------
__global__ void k_sm1(int n) {
    __shared__ float sh[256];
    int tid = threadIdx.x;
    float m = -1e30f;
    for (int i = blockIdx.x * 256 + tid; i < n; i += gridDim.x * 256)
        m = fmaxf(m, g_a[i]);
    sh[tid] = m; __syncthreads();
    for (int off = 128; off > 0; off >>= 1) {
        if (tid < off) sh[tid] = fmaxf(sh[tid], sh[tid + off]);
        __syncthreads();
    }
    float bm = sh[0]; __syncthreads();
    float s = 0.f;
    for (int i = blockIdx.x * 256 + tid; i < n; i += gridDim.x * 256)
        s += expf(g_a[i] - bm);
    sh[tid] = s; __syncthreads();
    for (int off = 128; off > 0; off >>= 1) {
        if (tid < off) sh[tid] += sh[tid + off];
        __syncthreads();
    }
    if (tid == 0) { g_pm[blockIdx.x] = bm; g_ps[blockIdx.x] = sh[0]; }
}

__global__ void k_sm2() {
    __shared__ float sh[SM1_BLOCKS];
    int tid = threadIdx.x;
    sh[tid] = g_pm[tid]; __syncthreads();
    for (int off = SM1_BLOCKS / 2; off > 0; off >>= 1) {
        if (tid < off) sh[tid] = fmaxf(sh[tid], sh[tid + off]);
        __syncthreads();
    }
    float M = sh[0]; __syncthreads();
    sh[tid] = g_ps[tid] * expf(g_pm[tid] - M); __syncthreads();
    for (int off = SM1_BLOCKS / 2; off > 0; off >>= 1) {
        if (tid < off) sh[tid] += sh[tid + off];
        __syncthreads();
    }
    if (tid == 0) { g_M = M; g_S = sh[0]; }
}

// ---------------------------------------------------------------------------
// K5/K6: zero + scatter
// ---------------------------------------------------------------------------
__global__ void k_zero(float* __restrict__ out, int n) {
    for (int i = blockIdx.x * blockDim.x + threadIdx.x; i < n;
         i += gridDim.x * blockDim.x)
        out[i] = 0.f;
}

__global__ void k_scatter(const int* __restrict__ ei,
                          const float* __restrict__ h,
                          float* __restrict__ out, int n_edges) {
    int gw = (blockIdx.x * blockDim.x + threadIdx.x) >> 5;
    int lane = threadIdx.x & 31;
    int nw = (gridDim.x * blockDim.x) >> 5;
    float M = g_M;
    float invS = 1.0f / g_S;
    for (int e = gw; e < n_edges; e += nw) {
        int r = ei[e];
        int c = ei[n_edges + e];
        float alpha = expf(g_a[e] - M) * invS;
        float4 hv = reinterpret_cast<const float4*>(h + (size_t)c * HID)[lane];
        float* op = out + (size_t)r * HID + lane * 4;
        atomicAdd(op + 0, alpha * hv.x);
        atomicAdd(op + 1, alpha * hv.y);
        atomicAdd(op + 2, alpha * hv.z);
        atomicAdd(op + 3, alpha * hv.w);
    }
}

// ---------------------------------------------------------------------------
extern "C" void kernel_launch(void* const* d_in, const int* in_sizes, int n_in,
                              void* d_out, int out_size) {
    const float* h  = (const float*)d_in[0];
    const int*   ei = (const int*)d_in[1];
    const float* ea = (const float*)d_in[2];
    const float* W1 = (const float*)d_in[3];
    const float* b1 = (const float*)d_in[4];
    const float* W2 = (const float*)d_in[5];
    const float* b2 = (const float*)d_in[6];
    float* out = (float*)d_out;

    int n_nodes = in_sizes[0] / HID;
    int n_edges = in_sizes[2] / HID;

    cudaFuncSetAttribute(k_tgemm, cudaFuncAttributeMaxDynamicSharedMemorySize, SMEM_TOTAL);
    cudaFuncSetAttribute(k_tedge, cudaFuncAttributeMaxDynamicSharedMemorySize, SMEM_TOTAL);

    float* d_u; cudaGetSymbolAddress((void**)&d_u, g_u);
    float* d_v; cudaGetSymbolAddress((void**)&d_v, g_v);

    int node_blocks = (n_nodes + 127) / 128;
    int edge_blocks = (n_edges + 127) / 128;

    k_zero<<<2048, 256>>>(out, n_nodes * HID);
    k_tgemm<<<node_blocks, 256, SMEM_TOTAL>>>(h, W1,             d_u, n_nodes);
    k_tgemm<<<node_blocks, 256, SMEM_TOTAL>>>(h, W1 + HID * HID, d_v, n_nodes);
    k_tedge<<<edge_blocks, 256, SMEM_TOTAL>>>(ea, W1 + 2 * HID * HID, ei, b1, W2, b2, n_edges);
    k_sm1<<<SM1_BLOCKS, 256>>>(n_edges);
    k_sm2<<<1, SM1_BLOCKS>>>();
    k_scatter<<<4096, 256>>>(ei, h, out, n_edges);
}